// round 6
// baseline (speedup 1.0000x reference)
#include <cuda_runtime.h>
#include <cstdint>

// ============================================================================
// untied LSTM cell, GB300 — plain sm_103 target (no 'a' features available:
// harness compiles with .target sm_103, so tcgen05/TMEM are off the table).
// Uses baseline tf32 mma.sync (m16n8k8) + cp.async 3-stage pipeline.
//
//   g[gate] = x @ Wx[g]^T + (h0 * maskH[g]) @ Wh[g]^T
//   pointwise: gates -> (h1, c1)
// ============================================================================

#define B_DIM 2048
#define H_DIM 1024
#define BH (B_DIM * H_DIM)

__device__ float g_scr[4u * BH];  // gate pre-activations (32 MB)
__device__ float g_hm [4u * BH];  // h0 * maskH[g]       (32 MB)

// ---------------- PTX helpers ----------------------------------------------

__device__ __forceinline__ uint32_t smem_u32(const void* p) {
    uint32_t a;
    asm("{ .reg .u64 t; cvta.to.shared.u64 t, %1; cvt.u32.u64 %0, t; }"
        : "=r"(a) : "l"(p));
    return a;
}

__device__ __forceinline__ void cp_async16(void* sdst, const void* gsrc) {
    asm volatile("cp.async.cg.shared.global [%0], [%1], 16;"
                 :: "r"(smem_u32(sdst)), "l"(gsrc));
}
__device__ __forceinline__ void cp_commit() {
    asm volatile("cp.async.commit_group;" ::: "memory");
}
template <int N>
__device__ __forceinline__ void cp_wait() {
    asm volatile("cp.async.wait_group %0;" :: "n"(N) : "memory");
}

__device__ __forceinline__ uint32_t tf32r(float f) {   // round-to-nearest tf32
    uint32_t u;
    asm("cvt.rna.tf32.f32 %0, %1;" : "=r"(u) : "f"(f));
    return u;
}

__device__ __forceinline__ void mma_tf32(float* c, const uint32_t* a,
                                         const uint32_t* b) {
    asm volatile(
        "mma.sync.aligned.m16n8k8.row.col.f32.tf32.tf32.f32 "
        "{%0,%1,%2,%3}, {%4,%5,%6,%7}, {%8,%9}, {%0,%1,%2,%3};"
        : "+f"(c[0]), "+f"(c[1]), "+f"(c[2]), "+f"(c[3])
        : "r"(a[0]), "r"(a[1]), "r"(a[2]), "r"(a[3]), "r"(b[0]), "r"(b[1]));
}

// ---------------- GEMM config ----------------------------------------------

static constexpr int TM = 128, TN = 128, TK = 32;
static constexpr int STAGES = 3;
static constexpr int STRIDE = 36;                        // floats/row (pad 32->36)
static constexpr int A_FLOATS = 128 * STRIDE;            // per stage (A or B)
static constexpr int STAGE_FLOATS = 2 * A_FLOATS;
static constexpr int SMEM_BYTES = STAGES * STAGE_FLOATS * 4;  // 110,592 B

// ---------------- GEMM kernel ----------------------------------------------

__global__ void __launch_bounds__(256, 2)
lstm_gemm(const float* __restrict__ x,
          const float* __restrict__ wxi, const float* __restrict__ wxf,
          const float* __restrict__ wxc, const float* __restrict__ wxo,
          const float* __restrict__ whi, const float* __restrict__ whf,
          const float* __restrict__ whc, const float* __restrict__ who)
{
    extern __shared__ float sm[];
    const int tid  = threadIdx.x;
    const int lane = tid & 31;
    const int wid  = tid >> 5;
    const int wm   = wid >> 2;          // 0..1  (M warps)
    const int wn   = wid & 3;           // 0..3  (N warps)
    const int n_tile = blockIdx.x;      // 0..7
    const int m_tile = blockIdx.y;      // 0..15
    const int gate   = blockIdx.z;      // 0..3

    const float* wx = gate == 0 ? wxi : gate == 1 ? wxf : gate == 2 ? wxc : wxo;
    const float* wh = gate == 0 ? whi : gate == 1 ? whf : gate == 2 ? whc : who;
    const float* hm = g_hm + (size_t)gate * BH;

    const int arow0 = m_tile * TM;
    const int brow0 = n_tile * TN;

    // stage s: A at sm + s*STAGE_FLOATS, B at + A_FLOATS
    auto issue = [&](int chunk, int stage) {
        const int kc = (chunk & 31) * TK;
        const float* Asrc = (chunk < 32) ? x : hm;
        const float* Bsrc = (chunk < 32) ? wx : wh;
        float* As = sm + stage * STAGE_FLOATS;
        float* Bs = As + A_FLOATS;
        #pragma unroll
        for (int r = 0; r < 4; ++r) {
            const int pos = tid + r * 256;          // 0..1023 float4 slots
            const int row = pos >> 3, c4 = pos & 7;
            cp_async16(As + row * STRIDE + c4 * 4,
                       Asrc + (size_t)(arow0 + row) * 1024 + kc + c4 * 4);
            cp_async16(Bs + row * STRIDE + c4 * 4,
                       Bsrc + (size_t)(brow0 + row) * 1024 + kc + c4 * 4);
        }
    };

    float acc[4][4][4];
    #pragma unroll
    for (int i = 0; i < 4; ++i)
        #pragma unroll
        for (int j = 0; j < 4; ++j)
            acc[i][j][0] = acc[i][j][1] = acc[i][j][2] = acc[i][j][3] = 0.f;

    // prologue: chunks 0,1 in flight
    issue(0, 0); cp_commit();
    issue(1, 1); cp_commit();

    for (int c = 0; c < 64; ++c) {
        cp_wait<1>();          // chunk c arrived (this thread's copies)
        __syncthreads();       // ...and everyone's

        const float* As = sm + (c % STAGES) * STAGE_FLOATS;
        const float* Bs = As + A_FLOATS;
        const float* ab = As + (wm * 64 + (lane >> 2)) * STRIDE + (lane & 3);
        const float* bb = Bs + (wn * 32 + (lane >> 2)) * STRIDE + (lane & 3);

        #pragma unroll
        for (int ks = 0; ks < 4; ++ks) {
            uint32_t af[4][4], bf[4][2];
            #pragma unroll
            for (int mf = 0; mf < 4; ++mf) {
                const float* p = ab + mf * 16 * STRIDE + ks * 8;
                af[mf][0] = tf32r(p[0]);
                af[mf][1] = tf32r(p[8 * STRIDE]);
                af[mf][2] = tf32r(p[4]);
                af[mf][3] = tf32r(p[8 * STRIDE + 4]);
            }
            #pragma unroll
            for (int nf = 0; nf < 4; ++nf) {
                const float* p = bb + nf * 8 * STRIDE + ks * 8;
                bf[nf][0] = tf32r(p[0]);
                bf[nf][1] = tf32r(p[4]);
            }
            #pragma unroll
            for (int mf = 0; mf < 4; ++mf)
                #pragma unroll
                for (int nf = 0; nf < 4; ++nf)
                    mma_tf32(acc[mf][nf], af[mf], bf[nf]);
        }

        if (c + 2 < 64) issue(c + 2, (c + 2) % STAGES);
        cp_commit();           // empty groups keep wait<1> semantics uniform
    }

    // epilogue: write pre-activations to scratch
    const int g = lane >> 2, t2 = (lane & 3) * 2;
    #pragma unroll
    for (int mf = 0; mf < 4; ++mf) {
        const int row = arow0 + wm * 64 + mf * 16 + g;
        float* orow = g_scr + ((size_t)gate * B_DIM + row) * H_DIM + brow0;
        #pragma unroll
        for (int nf = 0; nf < 4; ++nf) {
            const int col = wn * 32 + nf * 8 + t2;
            *(float2*)(orow + col) =
                make_float2(acc[mf][nf][0], acc[mf][nf][1]);
            *(float2*)(orow + col + 8 * H_DIM) =
                make_float2(acc[mf][nf][2], acc[mf][nf][3]);
        }
    }
}

// ---------------- pre-pass: hm[g] = h0 * maskH[g] ---------------------------

__global__ void __launch_bounds__(256)
hm_kernel(const float* __restrict__ h0,
          const float* __restrict__ mi, const float* __restrict__ mf,
          const float* __restrict__ mc, const float* __restrict__ mo)
{
    const int i = blockIdx.x * blockDim.x + threadIdx.x;   // over BH/4
    if (i >= BH / 4) return;
    const float4 h = ((const float4*)h0)[i];
    const float4 M[4] = { ((const float4*)mi)[i], ((const float4*)mf)[i],
                          ((const float4*)mc)[i], ((const float4*)mo)[i] };
    #pragma unroll
    for (int gate = 0; gate < 4; ++gate) {
        float4 o = make_float4(h.x * M[gate].x, h.y * M[gate].y,
                               h.z * M[gate].z, h.w * M[gate].w);
        ((float4*)(g_hm + (size_t)gate * BH))[i] = o;
    }
}

// ---------------- pointwise LSTM epilogue -----------------------------------

__device__ __forceinline__ float sigf(float v) {
    return 1.0f / (1.0f + __expf(-v));
}

__global__ void __launch_bounds__(256)
lstm_pointwise(const float* __restrict__ c0,
               const float* __restrict__ bi, const float* __restrict__ bf,
               const float* __restrict__ bc, const float* __restrict__ bo,
               const float* __restrict__ maskC, float* __restrict__ out)
{
    const int i4 = blockIdx.x * blockDim.x + threadIdx.x;   // over BH/4
    if (i4 >= BH / 4) return;
    const int k4 = i4 & (H_DIM / 4 - 1);

    const float4 GI = ((const float4*)(g_scr + 0 * (size_t)BH))[i4];
    const float4 GF = ((const float4*)(g_scr + 1 * (size_t)BH))[i4];
    const float4 GC = ((const float4*)(g_scr + 2 * (size_t)BH))[i4];
    const float4 GO = ((const float4*)(g_scr + 3 * (size_t)BH))[i4];
    const float4 BI = ((const float4*)bi)[k4];
    const float4 BF = ((const float4*)bf)[k4];
    const float4 BC = ((const float4*)bc)[k4];
    const float4 BO = ((const float4*)bo)[k4];
    const float4 C0 = ((const float4*)c0)[i4];
    const float4 MC = ((const float4*)maskC)[i4];

    float4 h1, c1;
#define LSTM_DO(c) { \
        const float I = sigf(GI.c + BI.c); \
        const float F = sigf(GF.c + BF.c); \
        const float C = tanhf(GC.c + BC.c) * MC.c; \
        const float O = sigf(GO.c + BO.c); \
        const float cc = F * C0.c + I * C; \
        c1.c = cc; h1.c = O * tanhf(cc); }
    LSTM_DO(x) LSTM_DO(y) LSTM_DO(z) LSTM_DO(w)
#undef LSTM_DO

    ((float4*)out)[i4]          = h1;   // h1 at [0, BH)
    ((float4*)out)[BH / 4 + i4] = c1;   // c1 at [BH, 2*BH)
}

// ---------------- launch ----------------------------------------------------

extern "C" void kernel_launch(void* const* d_in, const int* in_sizes, int n_in,
                              void* d_out, int out_size)
{
    const float* x     = (const float*)d_in[0];
    const float* h0    = (const float*)d_in[1];
    const float* c0    = (const float*)d_in[2];
    const float* w_xi  = (const float*)d_in[3];
    const float* w_xf  = (const float*)d_in[4];
    const float* w_xc  = (const float*)d_in[5];
    const float* w_xo  = (const float*)d_in[6];
    const float* w_hi  = (const float*)d_in[7];
    const float* w_hf  = (const float*)d_in[8];
    const float* w_hc  = (const float*)d_in[9];
    const float* w_ho  = (const float*)d_in[10];
    const float* b_i   = (const float*)d_in[11];
    const float* b_f   = (const float*)d_in[12];
    const float* b_c   = (const float*)d_in[13];
    const float* b_o   = (const float*)d_in[14];
    const float* mHI   = (const float*)d_in[15];
    const float* mHF   = (const float*)d_in[16];
    const float* mHC   = (const float*)d_in[17];
    const float* mHO   = (const float*)d_in[18];
    const float* maskC = (const float*)d_in[19];

    const int n4 = BH / 4;
    hm_kernel<<<(n4 + 255) / 256, 256>>>(h0, mHI, mHF, mHC, mHO);

    cudaFuncSetAttribute(lstm_gemm,
                         cudaFuncAttributeMaxDynamicSharedMemorySize, SMEM_BYTES);
    dim3 grid(H_DIM / TN, B_DIM / TM, 4);   // (8, 16, 4) = 512 CTAs
    lstm_gemm<<<grid, 256, SMEM_BYTES>>>(
        x, w_xi, w_xf, w_xc, w_xo, w_hi, w_hf, w_hc, w_ho);

    lstm_pointwise<<<(n4 + 255) / 256, 256>>>(c0, b_i, b_f, b_c, b_o, maskC,
                                              (float*)d_out);
}

// round 7
// speedup vs baseline: 1.0119x; 1.0119x over previous
#include <cuda_runtime.h>
#include <cstdint>

// ============================================================================
// untied LSTM cell, GB300 — plain sm_103 target (harness compiles .target
// sm_103: no tcgen05). tf32 mma.sync m16n8k8 + cp.async 3-stage pipeline.
//
// R7 changes vs R6 (272.9us): CTA tile 128x256 (was 128x128), warp tile 64x64
// (was 64x32). Halves L2 traffic per FLOP (1.07GB -> 786MB), 2x FLOPs per
// sync barrier, 128 independent accumulators per thread for ILP.
// ============================================================================

#define B_DIM 2048
#define H_DIM 1024
#define BH (B_DIM * H_DIM)

__device__ float g_scr[4u * BH];  // gate pre-activations (32 MB)
__device__ float g_hm [4u * BH];  // h0 * maskH[g]       (32 MB)

// ---------------- PTX helpers ----------------------------------------------

__device__ __forceinline__ uint32_t smem_u32(const void* p) {
    uint32_t a;
    asm("{ .reg .u64 t; cvta.to.shared.u64 t, %1; cvt.u32.u64 %0, t; }"
        : "=r"(a) : "l"(p));
    return a;
}

__device__ __forceinline__ void cp_async16(void* sdst, const void* gsrc) {
    asm volatile("cp.async.cg.shared.global [%0], [%1], 16;"
                 :: "r"(smem_u32(sdst)), "l"(gsrc));
}
__device__ __forceinline__ void cp_commit() {
    asm volatile("cp.async.commit_group;" ::: "memory");
}
template <int N>
__device__ __forceinline__ void cp_wait() {
    asm volatile("cp.async.wait_group %0;" :: "n"(N) : "memory");
}

__device__ __forceinline__ uint32_t tf32r(float f) {   // round-to-nearest tf32
    uint32_t u;
    asm("cvt.rna.tf32.f32 %0, %1;" : "=r"(u) : "f"(f));
    return u;
}

__device__ __forceinline__ void mma_tf32(float* c, const uint32_t* a,
                                         const uint32_t* b) {
    asm volatile(
        "mma.sync.aligned.m16n8k8.row.col.f32.tf32.tf32.f32 "
        "{%0,%1,%2,%3}, {%4,%5,%6,%7}, {%8,%9}, {%0,%1,%2,%3};"
        : "+f"(c[0]), "+f"(c[1]), "+f"(c[2]), "+f"(c[3])
        : "r"(a[0]), "r"(a[1]), "r"(a[2]), "r"(a[3]), "r"(b[0]), "r"(b[1]));
}

// ---------------- GEMM config ----------------------------------------------

static constexpr int TM = 128, TN = 256, TK = 32;
static constexpr int STAGES = 3;
static constexpr int STRIDE = 36;                    // floats/row (pad 32->36)
static constexpr int A_FLOATS = TM * STRIDE;         // 4608
static constexpr int B_FLOATS = TN * STRIDE;         // 9216
static constexpr int STAGE_FLOATS = A_FLOATS + B_FLOATS;      // 13824
static constexpr int SMEM_BYTES = STAGES * STAGE_FLOATS * 4;  // 165,888 B

// ---------------- GEMM kernel ----------------------------------------------

__global__ void __launch_bounds__(256, 1)
lstm_gemm(const float* __restrict__ x,
          const float* __restrict__ wxi, const float* __restrict__ wxf,
          const float* __restrict__ wxc, const float* __restrict__ wxo,
          const float* __restrict__ whi, const float* __restrict__ whf,
          const float* __restrict__ whc, const float* __restrict__ who)
{
    extern __shared__ float sm[];
    const int tid  = threadIdx.x;
    const int lane = tid & 31;
    const int wid  = tid >> 5;
    const int wm   = wid >> 2;          // 0..1  (M warps, 64 rows each)
    const int wn   = wid & 3;           // 0..3  (N warps, 64 cols each)
    const int n_tile = blockIdx.x;      // 0..3
    const int m_tile = blockIdx.y;      // 0..15
    const int gate   = blockIdx.z;      // 0..3

    const float* wx = gate == 0 ? wxi : gate == 1 ? wxf : gate == 2 ? wxc : wxo;
    const float* wh = gate == 0 ? whi : gate == 1 ? whf : gate == 2 ? whc : who;
    const float* hm = g_hm + (size_t)gate * BH;

    const int arow0 = m_tile * TM;
    const int brow0 = n_tile * TN;

    auto issue = [&](int chunk, int stage) {
        const int kc = (chunk & 31) * TK;
        const float* Asrc = (chunk < 32) ? x : hm;
        const float* Bsrc = (chunk < 32) ? wx : wh;
        float* As = sm + stage * STAGE_FLOATS;
        float* Bs = As + A_FLOATS;
        #pragma unroll
        for (int r = 0; r < 4; ++r) {               // A: 1024 float4 slots
            const int pos = tid + r * 256;
            const int row = pos >> 3, c4 = pos & 7;
            cp_async16(As + row * STRIDE + c4 * 4,
                       Asrc + (size_t)(arow0 + row) * 1024 + kc + c4 * 4);
        }
        #pragma unroll
        for (int r = 0; r < 8; ++r) {               // B: 2048 float4 slots
            const int pos = tid + r * 256;
            const int row = pos >> 3, c4 = pos & 7;
            cp_async16(Bs + row * STRIDE + c4 * 4,
                       Bsrc + (size_t)(brow0 + row) * 1024 + kc + c4 * 4);
        }
    };

    float acc[4][8][4];
    #pragma unroll
    for (int i = 0; i < 4; ++i)
        #pragma unroll
        for (int j = 0; j < 8; ++j)
            #pragma unroll
            for (int k = 0; k < 4; ++k) acc[i][j][k] = 0.f;

    issue(0, 0); cp_commit();
    issue(1, 1); cp_commit();

    for (int c = 0; c < 64; ++c) {
        cp_wait<1>();
        __syncthreads();

        const float* As = sm + (c % STAGES) * STAGE_FLOATS;
        const float* Bs = As + A_FLOATS;
        const float* ab = As + (wm * 64 + (lane >> 2)) * STRIDE + (lane & 3);
        const float* bb = Bs + (wn * 64 + (lane >> 2)) * STRIDE + (lane & 3);

        #pragma unroll
        for (int ks = 0; ks < 4; ++ks) {
            uint32_t af[4][4], bf[8][2];
            #pragma unroll
            for (int mf = 0; mf < 4; ++mf) {
                const float* p = ab + mf * 16 * STRIDE + ks * 8;
                af[mf][0] = tf32r(p[0]);
                af[mf][1] = tf32r(p[8 * STRIDE]);
                af[mf][2] = tf32r(p[4]);
                af[mf][3] = tf32r(p[8 * STRIDE + 4]);
            }
            #pragma unroll
            for (int nf = 0; nf < 8; ++nf) {
                const float* p = bb + nf * 8 * STRIDE + ks * 8;
                bf[nf][0] = tf32r(p[0]);
                bf[nf][1] = tf32r(p[4]);
            }
            #pragma unroll
            for (int mf = 0; mf < 4; ++mf)
                #pragma unroll
                for (int nf = 0; nf < 8; ++nf)
                    mma_tf32(acc[mf][nf], af[mf], bf[nf]);
        }

        if (c + 2 < 64) issue(c + 2, (c + 2) % STAGES);
        cp_commit();   // empty groups keep wait<1> accounting uniform
    }

    // epilogue: write pre-activations
    const int g = lane >> 2, t2 = (lane & 3) * 2;
    #pragma unroll
    for (int mf = 0; mf < 4; ++mf) {
        const int row = arow0 + wm * 64 + mf * 16 + g;
        float* orow = g_scr + ((size_t)gate * B_DIM + row) * H_DIM + brow0;
        #pragma unroll
        for (int nf = 0; nf < 8; ++nf) {
            const int col = wn * 64 + nf * 8 + t2;
            *(float2*)(orow + col) =
                make_float2(acc[mf][nf][0], acc[mf][nf][1]);
            *(float2*)(orow + col + 8 * H_DIM) =
                make_float2(acc[mf][nf][2], acc[mf][nf][3]);
        }
    }
}

// ---------------- pre-pass: hm[g] = h0 * maskH[g] ---------------------------

__global__ void __launch_bounds__(256)
hm_kernel(const float* __restrict__ h0,
          const float* __restrict__ mi, const float* __restrict__ mf,
          const float* __restrict__ mc, const float* __restrict__ mo)
{
    const int i = blockIdx.x * blockDim.x + threadIdx.x;   // over BH/4
    if (i >= BH / 4) return;
    const float4 h = ((const float4*)h0)[i];
    const float4 M[4] = { ((const float4*)mi)[i], ((const float4*)mf)[i],
                          ((const float4*)mc)[i], ((const float4*)mo)[i] };
    #pragma unroll
    for (int gate = 0; gate < 4; ++gate) {
        float4 o = make_float4(h.x * M[gate].x, h.y * M[gate].y,
                               h.z * M[gate].z, h.w * M[gate].w);
        ((float4*)(g_hm + (size_t)gate * BH))[i] = o;
    }
}

// ---------------- pointwise LSTM epilogue -----------------------------------

__device__ __forceinline__ float sigf(float v) {
    return 1.0f / (1.0f + __expf(-v));
}

__global__ void __launch_bounds__(256)
lstm_pointwise(const float* __restrict__ c0,
               const float* __restrict__ bi, const float* __restrict__ bf,
               const float* __restrict__ bc, const float* __restrict__ bo,
               const float* __restrict__ maskC, float* __restrict__ out)
{
    const int i4 = blockIdx.x * blockDim.x + threadIdx.x;   // over BH/4
    if (i4 >= BH / 4) return;
    const int k4 = i4 & (H_DIM / 4 - 1);

    const float4 GI = ((const float4*)(g_scr + 0 * (size_t)BH))[i4];
    const float4 GF = ((const float4*)(g_scr + 1 * (size_t)BH))[i4];
    const float4 GC = ((const float4*)(g_scr + 2 * (size_t)BH))[i4];
    const float4 GO = ((const float4*)(g_scr + 3 * (size_t)BH))[i4];
    const float4 BI = ((const float4*)bi)[k4];
    const float4 BF = ((const float4*)bf)[k4];
    const float4 BC = ((const float4*)bc)[k4];
    const float4 BO = ((const float4*)bo)[k4];
    const float4 C0 = ((const float4*)c0)[i4];
    const float4 MC = ((const float4*)maskC)[i4];

    float4 h1, c1;
#define LSTM_DO(c) { \
        const float I = sigf(GI.c + BI.c); \
        const float F = sigf(GF.c + BF.c); \
        const float C = tanhf(GC.c + BC.c) * MC.c; \
        const float O = sigf(GO.c + BO.c); \
        const float cc = F * C0.c + I * C; \
        c1.c = cc; h1.c = O * tanhf(cc); }
    LSTM_DO(x) LSTM_DO(y) LSTM_DO(z) LSTM_DO(w)
#undef LSTM_DO

    ((float4*)out)[i4]          = h1;   // h1 at [0, BH)
    ((float4*)out)[BH / 4 + i4] = c1;   // c1 at [BH, 2*BH)
}

// ---------------- launch ----------------------------------------------------

extern "C" void kernel_launch(void* const* d_in, const int* in_sizes, int n_in,
                              void* d_out, int out_size)
{
    const float* x     = (const float*)d_in[0];
    const float* h0    = (const float*)d_in[1];
    const float* c0    = (const float*)d_in[2];
    const float* w_xi  = (const float*)d_in[3];
    const float* w_xf  = (const float*)d_in[4];
    const float* w_xc  = (const float*)d_in[5];
    const float* w_xo  = (const float*)d_in[6];
    const float* w_hi  = (const float*)d_in[7];
    const float* w_hf  = (const float*)d_in[8];
    const float* w_hc  = (const float*)d_in[9];
    const float* w_ho  = (const float*)d_in[10];
    const float* b_i   = (const float*)d_in[11];
    const float* b_f   = (const float*)d_in[12];
    const float* b_c   = (const float*)d_in[13];
    const float* b_o   = (const float*)d_in[14];
    const float* mHI   = (const float*)d_in[15];
    const float* mHF   = (const float*)d_in[16];
    const float* mHC   = (const float*)d_in[17];
    const float* mHO   = (const float*)d_in[18];
    const float* maskC = (const float*)d_in[19];

    const int n4 = BH / 4;
    hm_kernel<<<(n4 + 255) / 256, 256>>>(h0, mHI, mHF, mHC, mHO);

    cudaFuncSetAttribute(lstm_gemm,
                         cudaFuncAttributeMaxDynamicSharedMemorySize, SMEM_BYTES);
    dim3 grid(H_DIM / TN, B_DIM / TM, 4);   // (4, 16, 4) = 256 CTAs
    lstm_gemm<<<grid, 256, SMEM_BYTES>>>(
        x, w_xi, w_xf, w_xc, w_xo, w_hi, w_hf, w_hc, w_ho);

    lstm_pointwise<<<(n4 + 255) / 256, 256>>>(c0, b_i, b_f, b_c, b_o, maskC,
                                              (float*)d_out);
}

// round 8
// speedup vs baseline: 1.9522x; 1.9293x over previous
#include <cuda_runtime.h>
#include <cuda_fp16.h>
#include <cstdint>

// ============================================================================
// untied LSTM cell, GB300 — plain sm_103 target (no tcgen05 allowed by the
// harness's ptxas target). R8: fp16 mma.sync m16n8k16 (4096 FLOP/instr, half
// the mma count of tf32 k8) + ldmatrix.x4 fragment loads + fp16 pre-converted
// operands (halves L2/SMEM traffic, removes all in-loop cvt).
//
//   g[gate] = x @ Wx[g]^T + (h0 * maskH[g]) @ Wh[g]^T
//   pointwise: gates -> (h1, c1)
// ============================================================================

#define B_DIM 2048
#define H_DIM 1024
#define BH (B_DIM * H_DIM)
#define HH (H_DIM * H_DIM)

__device__ float g_scr[4u * BH];                    // gate pre-acts (32 MB)
__device__ __align__(16) __half g_x16 [BH];         // x  in fp16 (4 MB)
__device__ __align__(16) __half g_hm16[4u * BH];    // h0*mask[g] fp16 (16 MB)
__device__ __align__(16) __half g_w16 [8u * HH];    // Wx[4],Wh[4] fp16 (16 MB)

// ---------------- PTX helpers ----------------------------------------------

__device__ __forceinline__ uint32_t smem_u32(const void* p) {
    uint32_t a;
    asm("{ .reg .u64 t; cvta.to.shared.u64 t, %1; cvt.u32.u64 %0, t; }"
        : "=r"(a) : "l"(p));
    return a;
}

__device__ __forceinline__ void cp_async16(void* sdst, const void* gsrc) {
    asm volatile("cp.async.cg.shared.global [%0], [%1], 16;"
                 :: "r"(smem_u32(sdst)), "l"(gsrc));
}
__device__ __forceinline__ void cp_commit() {
    asm volatile("cp.async.commit_group;" ::: "memory");
}
template <int N>
__device__ __forceinline__ void cp_wait() {
    asm volatile("cp.async.wait_group %0;" :: "n"(N) : "memory");
}

__device__ __forceinline__ void ldm_x4(uint32_t* r, uint32_t addr) {
    asm volatile("ldmatrix.sync.aligned.m8n8.x4.shared.b16 {%0,%1,%2,%3}, [%4];"
                 : "=r"(r[0]), "=r"(r[1]), "=r"(r[2]), "=r"(r[3]) : "r"(addr));
}

__device__ __forceinline__ void mma_f16(float* c, const uint32_t* a,
                                        const uint32_t* b) {
    asm volatile(
        "mma.sync.aligned.m16n8k16.row.col.f32.f16.f16.f32 "
        "{%0,%1,%2,%3}, {%4,%5,%6,%7}, {%8,%9}, {%0,%1,%2,%3};"
        : "+f"(c[0]), "+f"(c[1]), "+f"(c[2]), "+f"(c[3])
        : "r"(a[0]), "r"(a[1]), "r"(a[2]), "r"(a[3]), "r"(b[0]), "r"(b[1]));
}

__device__ __forceinline__ uint32_t pack_h2(float lo, float hi) {
    const __half2 h = __float22half2_rn(make_float2(lo, hi));
    return *(const uint32_t*)&h;
}

// ---------------- GEMM config ----------------------------------------------

static constexpr int TM = 128, TN = 256, TK = 64;   // fp16 K-chunk
static constexpr int STAGES = 3;
static constexpr int ROW_B = 144;                   // bytes/row: 128 + 16 pad
static constexpr int A_BYTES = TM * ROW_B;          // 18432
static constexpr int B_BYTES = TN * ROW_B;          // 36864
static constexpr int STAGE_BYTES = A_BYTES + B_BYTES;       // 55296
static constexpr int SMEM_BYTES = STAGES * STAGE_BYTES;     // 165888

// ---------------- GEMM kernel ----------------------------------------------

__global__ void __launch_bounds__(256, 1)
lstm_gemm()
{
    extern __shared__ char smc[];
    const int tid  = threadIdx.x;
    const int lane = tid & 31;
    const int wid  = tid >> 5;
    const int wm   = wid >> 2;          // 0..1  (M warps, 64 rows)
    const int wn   = wid & 3;           // 0..3  (N warps, 64 cols)
    const int n_tile = blockIdx.x;      // 0..3
    const int m_tile = blockIdx.y;      // 0..15
    const int gate   = blockIdx.z;      // 0..3

    const int arow0 = m_tile * TM;
    const int brow0 = n_tile * TN;
    const __half* xsrc  = g_x16;
    const __half* hsrc  = g_hm16 + (size_t)gate * BH;
    const __half* wxsrc = g_w16 + (size_t)gate * HH;
    const __half* whsrc = g_w16 + (size_t)(4 + gate) * HH;

    // 32 chunks of K=64: 0..15 from x/Wx, 16..31 from hm/Wh
    auto issue = [&](int chunk, int stage) {
        const int kc = (chunk & 15) * TK;                 // halves
        const __half* Asrc = (chunk < 16) ? xsrc : hsrc;
        const __half* Bsrc = (chunk < 16) ? wxsrc : whsrc;
        char* As = smc + stage * STAGE_BYTES;
        char* Bs = As + A_BYTES;
        #pragma unroll
        for (int r = 0; r < 4; ++r) {                     // A: 1024 x 16B
            const int pos = tid + r * 256;
            const int row = pos >> 3, c = pos & 7;
            cp_async16(As + row * ROW_B + c * 16,
                       (const char*)(Asrc + (size_t)(arow0 + row) * 1024 + kc)
                           + c * 16);
        }
        #pragma unroll
        for (int r = 0; r < 8; ++r) {                     // B: 2048 x 16B
            const int pos = tid + r * 256;
            const int row = pos >> 3, c = pos & 7;
            cp_async16(Bs + row * ROW_B + c * 16,
                       (const char*)(Bsrc + (size_t)(brow0 + row) * 1024 + kc)
                           + c * 16);
        }
    };

    float acc[4][8][4];
    #pragma unroll
    for (int i = 0; i < 4; ++i)
        #pragma unroll
        for (int j = 0; j < 8; ++j)
            #pragma unroll
            for (int k = 0; k < 4; ++k) acc[i][j][k] = 0.f;

    issue(0, 0); cp_commit();
    issue(1, 1); cp_commit();

    // ldmatrix lane-offset precompute (bytes within a stage)
    // A x4: lanes 0-15 -> rows 0-15 (k0), lanes 16-31 -> rows 0-15 (k+8, +16B)
    const uint32_t a_lane =
        (uint32_t)((wm * 64 + (lane & 15)) * ROW_B + (lane >> 4) * 16);
    // B x4: tiles {nf:k0, nf:k8, nf+1:k0, nf+1:k8}
    const uint32_t b_lane =
        (uint32_t)((wn * 64 + (lane & 7) + ((lane >> 4) << 3)) * ROW_B +
                   ((lane >> 3) & 1) * 16);
    const uint32_t sm_base = smem_u32(smc);

    for (int c = 0; c < 32; ++c) {
        cp_wait<1>();
        __syncthreads();

        const uint32_t stg = sm_base + (c % STAGES) * STAGE_BYTES;
        const uint32_t a_base = stg + a_lane;
        const uint32_t b_base = stg + A_BYTES + b_lane;

        #pragma unroll
        for (int ks = 0; ks < 4; ++ks) {                  // K=16 per step
            uint32_t af[4][4], bf[8][2];
            #pragma unroll
            for (int mf = 0; mf < 4; ++mf)
                ldm_x4(af[mf], a_base + mf * 16 * ROW_B + ks * 32);
            #pragma unroll
            for (int nb = 0; nb < 4; ++nb) {
                uint32_t r[4];
                ldm_x4(r, b_base + nb * 16 * ROW_B + ks * 32);
                bf[2 * nb][0] = r[0]; bf[2 * nb][1] = r[1];
                bf[2 * nb + 1][0] = r[2]; bf[2 * nb + 1][1] = r[3];
            }
            #pragma unroll
            for (int mf = 0; mf < 4; ++mf)
                #pragma unroll
                for (int nf = 0; nf < 8; ++nf)
                    mma_f16(acc[mf][nf], af[mf], bf[nf]);
        }

        if (c + 2 < 32) issue(c + 2, (c + 2) % STAGES);
        cp_commit();   // empty groups keep wait<1> accounting uniform
    }

    // epilogue: write pre-activations (fp32 scratch)
    const int g = lane >> 2, t2 = (lane & 3) * 2;
    #pragma unroll
    for (int mf = 0; mf < 4; ++mf) {
        const int row = arow0 + wm * 64 + mf * 16 + g;
        float* orow = g_scr + ((size_t)gate * B_DIM + row) * H_DIM + brow0;
        #pragma unroll
        for (int nf = 0; nf < 8; ++nf) {
            const int col = wn * 64 + nf * 8 + t2;
            *(float2*)(orow + col) =
                make_float2(acc[mf][nf][0], acc[mf][nf][1]);
            *(float2*)(orow + col + 8 * H_DIM) =
                make_float2(acc[mf][nf][2], acc[mf][nf][3]);
        }
    }
}

// ---------------- pre-pass 1: x -> fp16, hm[g] = h0*maskH[g] -> fp16 --------

__global__ void __launch_bounds__(256)
hm_kernel(const float* __restrict__ x,  const float* __restrict__ h0,
          const float* __restrict__ mi, const float* __restrict__ mf,
          const float* __restrict__ mc, const float* __restrict__ mo)
{
    const int i = blockIdx.x * blockDim.x + threadIdx.x;   // over BH/4
    if (i >= BH / 4) return;

    const float4 xv = ((const float4*)x)[i];
    ((uint2*)g_x16)[i] = make_uint2(pack_h2(xv.x, xv.y), pack_h2(xv.z, xv.w));

    const float4 h = ((const float4*)h0)[i];
    const float4 M[4] = { ((const float4*)mi)[i], ((const float4*)mf)[i],
                          ((const float4*)mc)[i], ((const float4*)mo)[i] };
    #pragma unroll
    for (int gate = 0; gate < 4; ++gate) {
        ((uint2*)(g_hm16 + (size_t)gate * BH))[i] =
            make_uint2(pack_h2(h.x * M[gate].x, h.y * M[gate].y),
                       pack_h2(h.z * M[gate].z, h.w * M[gate].w));
    }
}

// ---------------- pre-pass 2: weights -> fp16 -------------------------------

__global__ void __launch_bounds__(256)
wconv_kernel(const float* __restrict__ wxi, const float* __restrict__ wxf,
             const float* __restrict__ wxc, const float* __restrict__ wxo,
             const float* __restrict__ whi, const float* __restrict__ whf,
             const float* __restrict__ whc, const float* __restrict__ who)
{
    // 512 blocks per matrix (HH / (256*8)), 8 floats per thread
    const int m = blockIdx.x >> 9;
    const float* src =
        m == 0 ? wxi : m == 1 ? wxf : m == 2 ? wxc : m == 3 ? wxo :
        m == 4 ? whi : m == 5 ? whf : m == 6 ? whc : who;
    const int off = ((blockIdx.x & 511) * 256 + threadIdx.x) * 8;
    const float4 v0 = *(const float4*)(src + off);
    const float4 v1 = *(const float4*)(src + off + 4);
    *(uint4*)(g_w16 + (size_t)m * HH + off) =
        make_uint4(pack_h2(v0.x, v0.y), pack_h2(v0.z, v0.w),
                   pack_h2(v1.x, v1.y), pack_h2(v1.z, v1.w));
}

// ---------------- pointwise LSTM epilogue -----------------------------------

__device__ __forceinline__ float sigf(float v) {
    return 1.0f / (1.0f + __expf(-v));
}

__global__ void __launch_bounds__(256)
lstm_pointwise(const float* __restrict__ c0,
               const float* __restrict__ bi, const float* __restrict__ bf,
               const float* __restrict__ bc, const float* __restrict__ bo,
               const float* __restrict__ maskC, float* __restrict__ out)
{
    const int i4 = blockIdx.x * blockDim.x + threadIdx.x;   // over BH/4
    if (i4 >= BH / 4) return;
    const int k4 = i4 & (H_DIM / 4 - 1);

    const float4 GI = ((const float4*)(g_scr + 0 * (size_t)BH))[i4];
    const float4 GF = ((const float4*)(g_scr + 1 * (size_t)BH))[i4];
    const float4 GC = ((const float4*)(g_scr + 2 * (size_t)BH))[i4];
    const float4 GO = ((const float4*)(g_scr + 3 * (size_t)BH))[i4];
    const float4 BI = ((const float4*)bi)[k4];
    const float4 BF = ((const float4*)bf)[k4];
    const float4 BC = ((const float4*)bc)[k4];
    const float4 BO = ((const float4*)bo)[k4];
    const float4 C0 = ((const float4*)c0)[i4];
    const float4 MC = ((const float4*)maskC)[i4];

    float4 h1, c1;
#define LSTM_DO(c) { \
        const float I = sigf(GI.c + BI.c); \
        const float F = sigf(GF.c + BF.c); \
        const float C = tanhf(GC.c + BC.c) * MC.c; \
        const float O = sigf(GO.c + BO.c); \
        const float cc = F * C0.c + I * C; \
        c1.c = cc; h1.c = O * tanhf(cc); }
    LSTM_DO(x) LSTM_DO(y) LSTM_DO(z) LSTM_DO(w)
#undef LSTM_DO

    ((float4*)out)[i4]          = h1;   // h1 at [0, BH)
    ((float4*)out)[BH / 4 + i4] = c1;   // c1 at [BH, 2*BH)
}

// ---------------- launch ----------------------------------------------------

extern "C" void kernel_launch(void* const* d_in, const int* in_sizes, int n_in,
                              void* d_out, int out_size)
{
    const float* x     = (const float*)d_in[0];
    const float* h0    = (const float*)d_in[1];
    const float* c0    = (const float*)d_in[2];
    const float* w_xi  = (const float*)d_in[3];
    const float* w_xf  = (const float*)d_in[4];
    const float* w_xc  = (const float*)d_in[5];
    const float* w_xo  = (const float*)d_in[6];
    const float* w_hi  = (const float*)d_in[7];
    const float* w_hf  = (const float*)d_in[8];
    const float* w_hc  = (const float*)d_in[9];
    const float* w_ho  = (const float*)d_in[10];
    const float* b_i   = (const float*)d_in[11];
    const float* b_f   = (const float*)d_in[12];
    const float* b_c   = (const float*)d_in[13];
    const float* b_o   = (const float*)d_in[14];
    const float* mHI   = (const float*)d_in[15];
    const float* mHF   = (const float*)d_in[16];
    const float* mHC   = (const float*)d_in[17];
    const float* mHO   = (const float*)d_in[18];
    const float* maskC = (const float*)d_in[19];

    const int n4 = BH / 4;
    hm_kernel<<<(n4 + 255) / 256, 256>>>(x, h0, mHI, mHF, mHC, mHO);
    wconv_kernel<<<8 * 512, 256>>>(w_xi, w_xf, w_xc, w_xo,
                                   w_hi, w_hf, w_hc, w_ho);

    cudaFuncSetAttribute(lstm_gemm,
                         cudaFuncAttributeMaxDynamicSharedMemorySize, SMEM_BYTES);
    dim3 grid(H_DIM / TN, B_DIM / TM, 4);   // (4, 16, 4) = 256 CTAs
    lstm_gemm<<<grid, 256, SMEM_BYTES>>>();

    lstm_pointwise<<<(n4 + 255) / 256, 256>>>(c0, b_i, b_f, b_c, b_o, maskC,
                                              (float*)d_out);
}

// round 9
// speedup vs baseline: 2.0269x; 1.0383x over previous
#include <cuda_runtime.h>
#include <cuda_fp16.h>
#include <cstdint>

// ============================================================================
// untied LSTM cell, GB300 — plain sm_103 target (no tcgen05 in this harness).
// fp16 mma.sync m16n8k16 + ldmatrix.x4, 4-stage cp.async pipeline.
// R9 vs R8 (139.8us): GEMM confirmed at legacy-HMMA instruction floor, so this
// round cuts auxiliary time: fp16 gate scratch (halves epilogue+pointwise
// traffic), fused hm+wconv pre-pass, leaner pointwise, 4-stage pipeline.
// ============================================================================

#define B_DIM 2048
#define H_DIM 1024
#define BH (B_DIM * H_DIM)
#define HH (H_DIM * H_DIM)

__device__ __align__(16) __half g_g16 [4u * BH];    // gate pre-acts fp16 (16MB)
__device__ __align__(16) __half g_x16 [BH];         // x fp16 (4 MB)
__device__ __align__(16) __half g_hm16[4u * BH];    // h0*mask[g] fp16 (16 MB)
__device__ __align__(16) __half g_w16 [8u * HH];    // Wx[4],Wh[4] fp16 (16 MB)

// ---------------- PTX helpers ----------------------------------------------

__device__ __forceinline__ uint32_t smem_u32(const void* p) {
    uint32_t a;
    asm("{ .reg .u64 t; cvta.to.shared.u64 t, %1; cvt.u32.u64 %0, t; }"
        : "=r"(a) : "l"(p));
    return a;
}

__device__ __forceinline__ void cp_async16(void* sdst, const void* gsrc) {
    asm volatile("cp.async.cg.shared.global [%0], [%1], 16;"
                 :: "r"(smem_u32(sdst)), "l"(gsrc));
}
__device__ __forceinline__ void cp_commit() {
    asm volatile("cp.async.commit_group;" ::: "memory");
}
template <int N>
__device__ __forceinline__ void cp_wait() {
    asm volatile("cp.async.wait_group %0;" :: "n"(N) : "memory");
}

__device__ __forceinline__ void ldm_x4(uint32_t* r, uint32_t addr) {
    asm volatile("ldmatrix.sync.aligned.m8n8.x4.shared.b16 {%0,%1,%2,%3}, [%4];"
                 : "=r"(r[0]), "=r"(r[1]), "=r"(r[2]), "=r"(r[3]) : "r"(addr));
}

__device__ __forceinline__ void mma_f16(float* c, const uint32_t* a,
                                        const uint32_t* b) {
    asm volatile(
        "mma.sync.aligned.m16n8k16.row.col.f32.f16.f16.f32 "
        "{%0,%1,%2,%3}, {%4,%5,%6,%7}, {%8,%9}, {%0,%1,%2,%3};"
        : "+f"(c[0]), "+f"(c[1]), "+f"(c[2]), "+f"(c[3])
        : "r"(a[0]), "r"(a[1]), "r"(a[2]), "r"(a[3]), "r"(b[0]), "r"(b[1]));
}

__device__ __forceinline__ uint32_t pack_h2(float lo, float hi) {
    const __half2 h = __float22half2_rn(make_float2(lo, hi));
    return *(const uint32_t*)&h;
}

// ---------------- GEMM config ----------------------------------------------

static constexpr int TM = 128, TN = 256, TK = 64;
static constexpr int STAGES = 4;
static constexpr int ROW_B = 144;                   // bytes/row: 128 + 16 pad
static constexpr int A_BYTES = TM * ROW_B;          // 18432
static constexpr int B_BYTES = TN * ROW_B;          // 36864
static constexpr int STAGE_BYTES = A_BYTES + B_BYTES;       // 55296
static constexpr int SMEM_BYTES = STAGES * STAGE_BYTES;     // 221184 (<227KB)

// ---------------- GEMM kernel ----------------------------------------------

__global__ void __launch_bounds__(256, 1)
lstm_gemm()
{
    extern __shared__ char smc[];
    const int tid  = threadIdx.x;
    const int lane = tid & 31;
    const int wid  = tid >> 5;
    const int wm   = wid >> 2;          // 0..1  (M warps, 64 rows)
    const int wn   = wid & 3;           // 0..3  (N warps, 64 cols)
    const int n_tile = blockIdx.x;      // 0..3
    const int m_tile = blockIdx.y;      // 0..15
    const int gate   = blockIdx.z;      // 0..3

    const int arow0 = m_tile * TM;
    const int brow0 = n_tile * TN;
    const __half* xsrc  = g_x16;
    const __half* hsrc  = g_hm16 + (size_t)gate * BH;
    const __half* wxsrc = g_w16 + (size_t)gate * HH;
    const __half* whsrc = g_w16 + (size_t)(4 + gate) * HH;

    // 32 chunks of K=64: 0..15 from x/Wx, 16..31 from hm/Wh
    auto issue = [&](int chunk, int stage) {
        const int kc = (chunk & 15) * TK;                 // halves
        const __half* Asrc = (chunk < 16) ? xsrc : hsrc;
        const __half* Bsrc = (chunk < 16) ? wxsrc : whsrc;
        char* As = smc + stage * STAGE_BYTES;
        char* Bs = As + A_BYTES;
        #pragma unroll
        for (int r = 0; r < 4; ++r) {                     // A: 1024 x 16B
            const int pos = tid + r * 256;
            const int row = pos >> 3, c = pos & 7;
            cp_async16(As + row * ROW_B + c * 16,
                       (const char*)(Asrc + (size_t)(arow0 + row) * 1024 + kc)
                           + c * 16);
        }
        #pragma unroll
        for (int r = 0; r < 8; ++r) {                     // B: 2048 x 16B
            const int pos = tid + r * 256;
            const int row = pos >> 3, c = pos & 7;
            cp_async16(Bs + row * ROW_B + c * 16,
                       (const char*)(Bsrc + (size_t)(brow0 + row) * 1024 + kc)
                           + c * 16);
        }
    };

    float acc[4][8][4];
    #pragma unroll
    for (int i = 0; i < 4; ++i)
        #pragma unroll
        for (int j = 0; j < 8; ++j)
            #pragma unroll
            for (int k = 0; k < 4; ++k) acc[i][j][k] = 0.f;

    issue(0, 0); cp_commit();
    issue(1, 1); cp_commit();
    issue(2, 2); cp_commit();

    // ldmatrix lane offsets (bytes within a stage)
    const uint32_t a_lane =
        (uint32_t)((wm * 64 + (lane & 15)) * ROW_B + (lane >> 4) * 16);
    const uint32_t b_lane =
        (uint32_t)((wn * 64 + (lane & 7) + ((lane >> 4) << 3)) * ROW_B +
                   ((lane >> 3) & 1) * 16);
    const uint32_t sm_base = smem_u32(smc);

    for (int c = 0; c < 32; ++c) {
        cp_wait<2>();
        __syncthreads();

        const uint32_t stg = sm_base + (c & 3) * STAGE_BYTES;
        const uint32_t a_base = stg + a_lane;
        const uint32_t b_base = stg + A_BYTES + b_lane;

        #pragma unroll
        for (int ks = 0; ks < 4; ++ks) {                  // K=16 per step
            uint32_t af[4][4], bf[8][2];
            #pragma unroll
            for (int mf = 0; mf < 4; ++mf)
                ldm_x4(af[mf], a_base + mf * 16 * ROW_B + ks * 32);
            #pragma unroll
            for (int nb = 0; nb < 4; ++nb) {
                uint32_t r[4];
                ldm_x4(r, b_base + nb * 16 * ROW_B + ks * 32);
                bf[2 * nb][0] = r[0]; bf[2 * nb][1] = r[1];
                bf[2 * nb + 1][0] = r[2]; bf[2 * nb + 1][1] = r[3];
            }
            #pragma unroll
            for (int mf = 0; mf < 4; ++mf)
                #pragma unroll
                for (int nf = 0; nf < 8; ++nf)
                    mma_f16(acc[mf][nf], af[mf], bf[nf]);
        }

        if (c + 3 < 32) issue(c + 3, (c + 3) & 3);
        cp_commit();   // uniform commits keep wait<2> accounting simple
    }

    // epilogue: pre-activations -> fp16 scratch
    const int g = lane >> 2, t2 = (lane & 3) * 2;
    #pragma unroll
    for (int mf = 0; mf < 4; ++mf) {
        const int row = arow0 + wm * 64 + mf * 16 + g;
        __half* orow = g_g16 + ((size_t)gate * B_DIM + row) * H_DIM + brow0;
        #pragma unroll
        for (int nf = 0; nf < 8; ++nf) {
            const int col = wn * 64 + nf * 8 + t2;
            *(uint32_t*)(orow + col) =
                pack_h2(acc[mf][nf][0], acc[mf][nf][1]);
            *(uint32_t*)(orow + col + 8 * H_DIM) =
                pack_h2(acc[mf][nf][2], acc[mf][nf][3]);
        }
    }
}

// ------- fused pre-pass: x->fp16, hm[g]=h0*mask[g]->fp16, weights->fp16 -----

__global__ void __launch_bounds__(256)
prep_kernel(const float* __restrict__ x,  const float* __restrict__ h0,
            const float* __restrict__ mi, const float* __restrict__ mf,
            const float* __restrict__ mc, const float* __restrict__ mo,
            const float* __restrict__ wxi, const float* __restrict__ wxf,
            const float* __restrict__ wxc, const float* __restrict__ wxo,
            const float* __restrict__ whi, const float* __restrict__ whf,
            const float* __restrict__ whc, const float* __restrict__ who)
{
    const int bid = blockIdx.x;
    if (bid < 2048) {                               // x + hm part (BH/4 elems)
        const int i = bid * 256 + threadIdx.x;
        const float4 xv = ((const float4*)x)[i];
        ((uint2*)g_x16)[i] =
            make_uint2(pack_h2(xv.x, xv.y), pack_h2(xv.z, xv.w));
        const float4 h = ((const float4*)h0)[i];
        const float4 M[4] = { ((const float4*)mi)[i], ((const float4*)mf)[i],
                              ((const float4*)mc)[i], ((const float4*)mo)[i] };
        #pragma unroll
        for (int gate = 0; gate < 4; ++gate) {
            ((uint2*)(g_hm16 + (size_t)gate * BH))[i] =
                make_uint2(pack_h2(h.x * M[gate].x, h.y * M[gate].y),
                           pack_h2(h.z * M[gate].z, h.w * M[gate].w));
        }
    } else {                                        // weight conversion part
        const int wb = bid - 2048;                  // 0..4095
        const int m = wb >> 9;                      // matrix 0..7
        const float* src =
            m == 0 ? wxi : m == 1 ? wxf : m == 2 ? wxc : m == 3 ? wxo :
            m == 4 ? whi : m == 5 ? whf : m == 6 ? whc : who;
        const int off = ((wb & 511) * 256 + threadIdx.x) * 8;
        const float4 v0 = *(const float4*)(src + off);
        const float4 v1 = *(const float4*)(src + off + 4);
        *(uint4*)(g_w16 + (size_t)m * HH + off) =
            make_uint4(pack_h2(v0.x, v0.y), pack_h2(v0.z, v0.w),
                       pack_h2(v1.x, v1.y), pack_h2(v1.z, v1.w));
    }
}

// ---------------- pointwise LSTM epilogue -----------------------------------

__device__ __forceinline__ float sigf(float v) {
    return 1.0f / (1.0f + __expf(-v));
}

__global__ void __launch_bounds__(256)
lstm_pointwise(const float* __restrict__ c0,
               const float* __restrict__ bi, const float* __restrict__ bf,
               const float* __restrict__ bc, const float* __restrict__ bo,
               const float* __restrict__ maskC, float* __restrict__ out)
{
    const int i4 = blockIdx.x * blockDim.x + threadIdx.x;   // over BH/4
    if (i4 >= BH / 4) return;
    const int k4 = i4 & (H_DIM / 4 - 1);

    // fp16 gate pre-acts: uint2 = 4 halves
    const uint2 gi = ((const uint2*)(g_g16 + 0 * (size_t)BH))[i4];
    const uint2 gf = ((const uint2*)(g_g16 + 1 * (size_t)BH))[i4];
    const uint2 gc = ((const uint2*)(g_g16 + 2 * (size_t)BH))[i4];
    const uint2 go = ((const uint2*)(g_g16 + 3 * (size_t)BH))[i4];
    const float2 GI0 = __half22float2(*(const __half2*)&gi.x);
    const float2 GI1 = __half22float2(*(const __half2*)&gi.y);
    const float2 GF0 = __half22float2(*(const __half2*)&gf.x);
    const float2 GF1 = __half22float2(*(const __half2*)&gf.y);
    const float2 GC0 = __half22float2(*(const __half2*)&gc.x);
    const float2 GC1 = __half22float2(*(const __half2*)&gc.y);
    const float2 GO0 = __half22float2(*(const __half2*)&go.x);
    const float2 GO1 = __half22float2(*(const __half2*)&go.y);

    const float4 BI = ((const float4*)bi)[k4];
    const float4 BF = ((const float4*)bf)[k4];
    const float4 BC = ((const float4*)bc)[k4];
    const float4 BO = ((const float4*)bo)[k4];
    const float4 C0 = ((const float4*)c0)[i4];
    const float4 MC = ((const float4*)maskC)[i4];

    float4 h1, c1;
#define LSTM_DO(gi_, gf_, gc_, go_, cb, cc_) { \
        const float I = sigf((gi_) + BI.cb); \
        const float F = sigf((gf_) + BF.cb); \
        const float C = tanhf((gc_) + BC.cb) * MC.cb; \
        const float O = sigf((go_) + BO.cb); \
        const float cc = F * C0.cb + I * C; \
        c1.cb = cc; h1.cb = O * tanhf(cc); (void)0; }
    LSTM_DO(GI0.x, GF0.x, GC0.x, GO0.x, x, 0)
    LSTM_DO(GI0.y, GF0.y, GC0.y, GO0.y, y, 1)
    LSTM_DO(GI1.x, GF1.x, GC1.x, GO1.x, z, 2)
    LSTM_DO(GI1.y, GF1.y, GC1.y, GO1.y, w, 3)
#undef LSTM_DO

    ((float4*)out)[i4]          = h1;   // h1 at [0, BH)
    ((float4*)out)[BH / 4 + i4] = c1;   // c1 at [BH, 2*BH)
}

// ---------------- launch ----------------------------------------------------

extern "C" void kernel_launch(void* const* d_in, const int* in_sizes, int n_in,
                              void* d_out, int out_size)
{
    const float* x     = (const float*)d_in[0];
    const float* h0    = (const float*)d_in[1];
    const float* c0    = (const float*)d_in[2];
    const float* w_xi  = (const float*)d_in[3];
    const float* w_xf  = (const float*)d_in[4];
    const float* w_xc  = (const float*)d_in[5];
    const float* w_xo  = (const float*)d_in[6];
    const float* w_hi  = (const float*)d_in[7];
    const float* w_hf  = (const float*)d_in[8];
    const float* w_hc  = (const float*)d_in[9];
    const float* w_ho  = (const float*)d_in[10];
    const float* b_i   = (const float*)d_in[11];
    const float* b_f   = (const float*)d_in[12];
    const float* b_c   = (const float*)d_in[13];
    const float* b_o   = (const float*)d_in[14];
    const float* mHI   = (const float*)d_in[15];
    const float* mHF   = (const float*)d_in[16];
    const float* mHC   = (const float*)d_in[17];
    const float* mHO   = (const float*)d_in[18];
    const float* maskC = (const float*)d_in[19];

    prep_kernel<<<2048 + 4096, 256>>>(x, h0, mHI, mHF, mHC, mHO,
                                      w_xi, w_xf, w_xc, w_xo,
                                      w_hi, w_hf, w_hc, w_ho);

    cudaFuncSetAttribute(lstm_gemm,
                         cudaFuncAttributeMaxDynamicSharedMemorySize, SMEM_BYTES);
    dim3 grid(H_DIM / TN, B_DIM / TM, 4);   // (4, 16, 4) = 256 CTAs
    lstm_gemm<<<grid, 256, SMEM_BYTES>>>();

    const int n4 = BH / 4;
    lstm_pointwise<<<(n4 + 255) / 256, 256>>>(c0, b_i, b_f, b_c, b_o, maskC,
                                              (float*)d_out);
}